// round 5
// baseline (speedup 1.0000x reference)
#include <cuda_runtime.h>
#include <math.h>

// ---------------------------------------------------------------------------
// Actor_Soft_Attention: B=65536, IN=128, HID=256, OUT=8
//
//   agents[b,n] = [s0 | s_{n+1}]  (n=0,1), dim 256
//   h_n = relu(agents_n @ W1^T + b1)         (shared half: t0 = s0 @ W1a^T)
//   e_n = relu(agents_n @ W2^T + b2)
//   a   = softmax over n (2-way, per channel)
//   h_i = a0*h_0 + a1*h_1
//   x   = relu([h_i | s0 s1 s2] @ W3^T + b3)   (K=640 -> 256)
//   out = tanh(x @ W4^T + b4)                  (256 -> 8)
//
// One fused kernel. BM=64 rows per block, 256 threads.
// A_s[64][644] holds the full layer-3 operand: cols [0,256)=h_i (written by
// phase 1), cols [256,640)=state. Weights streamed through SMEM tiles.
// ---------------------------------------------------------------------------

#define BM 64
#define AS 644                 // A_s row stride (640 + 4 pad)
#define WS 132                 // weight tile row stride (128 + 4 pad)
#define XS 66                  // xs tile row stride (64 + 2 pad)

#define A_FLOATS   (BM * AS)           // 41216
#define W_OFF      A_FLOATS
#define W_FLOATS   (2 * 32 * WS)       // 8448 (two 32x128 halves)
#define XS_OFF     (W_OFF + W_FLOATS)  // 49664
#define XS_FLOATS  (32 * XS)           // 2112
#define W4_OFF     (XS_OFF + XS_FLOATS)// 51776
#define W4_FLOATS  2048
#define SMEM_FLOATS (W4_OFF + W4_FLOATS) // 53824
#define SMEM_BYTES  (SMEM_FLOATS * 4)    // 215296 bytes

__device__ __forceinline__ float dot4(float4 a, float4 w, float acc) {
    acc = fmaf(a.x, w.x, acc);
    acc = fmaf(a.y, w.y, acc);
    acc = fmaf(a.z, w.z, acc);
    acc = fmaf(a.w, w.w, acc);
    return acc;
}

__global__ __launch_bounds__(256, 1)
void actor_soft_attention_kernel(
    const float* __restrict__ state,
    const float* __restrict__ W1, const float* __restrict__ b1,
    const float* __restrict__ W2, const float* __restrict__ b2,
    const float* __restrict__ W3, const float* __restrict__ b3,
    const float* __restrict__ W4, const float* __restrict__ b4,
    float* __restrict__ out)
{
    extern __shared__ float sm[];
    float* A_s  = sm;            // [64][644]
    float* W_s  = sm + W_OFF;    // [2][32][132]
    float* xs_s = sm + XS_OFF;   // [32][66]
    float* W4t  = sm + W4_OFF;   // [256][8]  (W4 transposed)

    const int t  = threadIdx.x;
    const int tr = t & 15;       // row group: rows tr + 16*i, i=0..3
    const int tc = t >> 4;       // ch group:  channels tc, tc+16 within a 32-tile
    const long long row_base = (long long)blockIdx.x * BM;

    // --- W4 transposed into smem: W4t[j*8+o] = W4[o*256+j] ---
    for (int i = t; i < 2048; i += 256) {
        int o = i >> 8, j = i & 255;
        W4t[j * 8 + o] = W4[i];
    }

    // --- state tile -> A_s[r][256..639] (tile is contiguous 64*384 floats) ---
    {
        const float4* gs = (const float4*)(state + row_base * 384);
        for (int i4 = t; i4 < 6144; i4 += 256) {
            int r = i4 / 96;
            int q = (i4 % 96) * 4;
            float4 v = gs[i4];
            *(float4*)&A_s[r * AS + 256 + q] = v;
        }
    }
    __syncthreads();

    // =====================================================================
    // Phase 1: layer 1 (W1, W2) + 2-way softmax combine -> h_i into A_s[:,0:256)
    // =====================================================================
    for (int c0 = 0; c0 < 256; c0 += 32) {
        // ---- stage W1 tile: rows c0..c0+31, split into [:,0:128) and [:,128:256) ----
        {
            const float4* gw = (const float4*)(W1 + (size_t)c0 * 256);
            for (int i4 = t; i4 < 2048; i4 += 256) {
                int ch = i4 >> 6;
                int d  = (i4 & 63) * 4;
                float4 v = gw[i4];
                int part = d >> 7;
                int dd   = d & 127;
                *(float4*)&W_s[part * (32 * WS) + ch * WS + dd] = v;
            }
        }
        __syncthreads();

        float t0[4][2] = {}, t1[4][2] = {}, t2[4][2] = {};
        #pragma unroll 4
        for (int k = 0; k < 128; k += 4) {
            float4 wa0 = *(float4*)&W_s[tc * WS + k];
            float4 wa1 = *(float4*)&W_s[(tc + 16) * WS + k];
            float4 wb0 = *(float4*)&W_s[32 * WS + tc * WS + k];
            float4 wb1 = *(float4*)&W_s[32 * WS + (tc + 16) * WS + k];
            #pragma unroll
            for (int i = 0; i < 4; i++) {
                const float* ap = &A_s[(tr + 16 * i) * AS];
                float4 a0 = *(float4*)&ap[256 + k];
                float4 a1 = *(float4*)&ap[384 + k];
                float4 a2 = *(float4*)&ap[512 + k];
                t0[i][0] = dot4(a0, wa0, t0[i][0]);
                t0[i][1] = dot4(a0, wa1, t0[i][1]);
                t1[i][0] = dot4(a1, wb0, t1[i][0]);
                t1[i][1] = dot4(a1, wb1, t1[i][1]);
                t2[i][0] = dot4(a2, wb0, t2[i][0]);
                t2[i][1] = dot4(a2, wb1, t2[i][1]);
            }
        }
        __syncthreads();

        // ---- stage W2 tile (same layout) ----
        {
            const float4* gw = (const float4*)(W2 + (size_t)c0 * 256);
            for (int i4 = t; i4 < 2048; i4 += 256) {
                int ch = i4 >> 6;
                int d  = (i4 & 63) * 4;
                float4 v = gw[i4];
                int part = d >> 7;
                int dd   = d & 127;
                *(float4*)&W_s[part * (32 * WS) + ch * WS + dd] = v;
            }
        }
        __syncthreads();

        float u0[4][2] = {}, u1[4][2] = {}, u2[4][2] = {};
        #pragma unroll 4
        for (int k = 0; k < 128; k += 4) {
            float4 wa0 = *(float4*)&W_s[tc * WS + k];
            float4 wa1 = *(float4*)&W_s[(tc + 16) * WS + k];
            float4 wb0 = *(float4*)&W_s[32 * WS + tc * WS + k];
            float4 wb1 = *(float4*)&W_s[32 * WS + (tc + 16) * WS + k];
            #pragma unroll
            for (int i = 0; i < 4; i++) {
                const float* ap = &A_s[(tr + 16 * i) * AS];
                float4 a0 = *(float4*)&ap[256 + k];
                float4 a1 = *(float4*)&ap[384 + k];
                float4 a2 = *(float4*)&ap[512 + k];
                u0[i][0] = dot4(a0, wa0, u0[i][0]);
                u0[i][1] = dot4(a0, wa1, u0[i][1]);
                u1[i][0] = dot4(a1, wb0, u1[i][0]);
                u1[i][1] = dot4(a1, wb1, u1[i][1]);
                u2[i][0] = dot4(a2, wb0, u2[i][0]);
                u2[i][1] = dot4(a2, wb1, u2[i][1]);
            }
        }

        // ---- combine: relu, 2-way softmax over neighbors, write h_i ----
        float b1v0 = __ldg(&b1[c0 + tc]);
        float b1v1 = __ldg(&b1[c0 + tc + 16]);
        float b2v0 = __ldg(&b2[c0 + tc]);
        float b2v1 = __ldg(&b2[c0 + tc + 16]);
        #pragma unroll
        for (int i = 0; i < 4; i++) {
            #pragma unroll
            for (int j = 0; j < 2; j++) {
                float bb1 = j ? b1v1 : b1v0;
                float bb2 = j ? b2v1 : b2v0;
                float h0 = fmaxf(t0[i][j] + t1[i][j] + bb1, 0.0f);
                float h1 = fmaxf(t0[i][j] + t2[i][j] + bb1, 0.0f);
                float e0 = fmaxf(u0[i][j] + u1[i][j] + bb2, 0.0f);
                float e1 = fmaxf(u0[i][j] + u2[i][j] + bb2, 0.0f);
                float m  = fmaxf(e0, e1);
                float p0 = __expf(e0 - m);
                float p1 = __expf(e1 - m);
                float hi = (p0 * h0 + p1 * h1) / (p0 + p1);
                A_s[(tr + 16 * i) * AS + c0 + tc + 16 * j] = hi;
            }
        }
        __syncthreads();   // W_s reuse + h_i visibility
    }

    // =====================================================================
    // Phase 2 (W3, K=640) fused with Phase 3 (W4 -> 8 outputs, tanh)
    // =====================================================================
    float oacc0 = 0.0f, oacc1 = 0.0f;
    const int p0i = 2 * t;
    const int pr  = p0i >> 3;          // row 0..63 (same for both outputs)
    const int po0 = p0i & 7;
    const int po1 = (p0i + 1) & 7;

    for (int c0 = 0; c0 < 256; c0 += 32) {
        float x[4][2] = {};
        for (int k0 = 0; k0 < 640; k0 += 128) {
            // stage W3 chunk: rows c0..c0+31, cols k0..k0+127
            for (int i4 = t; i4 < 1024; i4 += 256) {
                int ch = i4 >> 5;
                int d  = (i4 & 31) * 4;
                float4 v = *(const float4*)&W3[(size_t)(c0 + ch) * 640 + k0 + d];
                *(float4*)&W_s[ch * WS + d] = v;
            }
            __syncthreads();
            #pragma unroll 4
            for (int k = 0; k < 128; k += 4) {
                float4 w0 = *(float4*)&W_s[tc * WS + k];
                float4 w1 = *(float4*)&W_s[(tc + 16) * WS + k];
                #pragma unroll
                for (int i = 0; i < 4; i++) {
                    float4 a = *(float4*)&A_s[(tr + 16 * i) * AS + k0 + k];
                    x[i][0] = dot4(a, w0, x[i][0]);
                    x[i][1] = dot4(a, w1, x[i][1]);
                }
            }
            __syncthreads();
        }
        // relu + bias, stage this 32-channel slice of xxx as [ch][row]
        float b3v0 = __ldg(&b3[c0 + tc]);
        float b3v1 = __ldg(&b3[c0 + tc + 16]);
        #pragma unroll
        for (int i = 0; i < 4; i++) {
            xs_s[tc * XS + tr + 16 * i]        = fmaxf(x[i][0] + b3v0, 0.0f);
            xs_s[(tc + 16) * XS + tr + 16 * i] = fmaxf(x[i][1] + b3v1, 0.0f);
        }
        __syncthreads();
        // phase-3 partial: out[r][o] += sum_j W4[o][c0+j] * xxx[r][c0+j]
        #pragma unroll
        for (int jj = 0; jj < 32; jj++) {
            float xv = xs_s[jj * XS + pr];
            oacc0 = fmaf(W4t[(c0 + jj) * 8 + po0], xv, oacc0);
            oacc1 = fmaf(W4t[(c0 + jj) * 8 + po1], xv, oacc1);
        }
        __syncthreads();
    }

    float r0 = tanhf(oacc0 + __ldg(&b4[po0]));
    float r1 = tanhf(oacc1 + __ldg(&b4[po1]));
    out[(row_base + pr) * 8 + po0] = r0;
    out[(row_base + pr) * 8 + po1] = r1;
}

// ---------------------------------------------------------------------------
// kernel_launch — graph-capturable, allocation-free.
// Input order (metadata): state, W1, b1, W2, b2, W3, b3, W4, b4
// ---------------------------------------------------------------------------
extern "C" void kernel_launch(void* const* d_in, const int* in_sizes, int n_in,
                              void* d_out, int out_size)
{
    const float* state = (const float*)d_in[0];
    const float* W1    = (const float*)d_in[1];
    const float* b1    = (const float*)d_in[2];
    const float* W2    = (const float*)d_in[3];
    const float* b2    = (const float*)d_in[4];
    const float* W3    = (const float*)d_in[5];
    const float* b3    = (const float*)d_in[6];
    const float* W4    = (const float*)d_in[7];
    const float* b4    = (const float*)d_in[8];
    float* out = (float*)d_out;

    const int B = in_sizes[0] / 384;          // 65536
    const int nblocks = B / BM;               // 1024

    // Idempotent; executes immediately (not a captured stream op).
    cudaFuncSetAttribute(actor_soft_attention_kernel,
                         cudaFuncAttributeMaxDynamicSharedMemorySize,
                         SMEM_BYTES);

    actor_soft_attention_kernel<<<nblocks, 256, SMEM_BYTES>>>(
        state, W1, b1, W2, b2, W3, b3, W4, b4, out);
}